// round 3
// baseline (speedup 1.0000x reference)
#include <cuda_runtime.h>
#include <cuda_bf16.h>
#include <math.h>

#define NB     4096
#define NG     16
#define NIN    1024
#define NHID   2048
#define NPROJ  256
#define NCHUNK 4096
#define OUTLD  (NG*NCHUNK)   /* 65536 */

// Scratch (device globals — no allocation allowed)
__device__ float g_h[(size_t)NG*NB*NHID];     // 512 MB: h, then overwritten with LN+GELU(h)
__device__ float g_qn[(size_t)NG*NB*NPROJ];   // 16 MB: normalized q
__device__ float g_coef[NG*NCHUNK];           // scale[g]/||Wv[g,v]||

__device__ __forceinline__ unsigned f2tf(float f){
  unsigned u;
  asm("cvt.rna.tf32.f32 %0, %1;" : "=r"(u) : "f"(f));
  return u;
}

__device__ __forceinline__ void mma8(float* c, const unsigned* a, const unsigned* b){
  asm volatile(
    "mma.sync.aligned.m16n8k8.row.col.f32.tf32.tf32.f32 "
    "{%0,%1,%2,%3}, {%4,%5,%6,%7}, {%8,%9}, {%0,%1,%2,%3};\n"
    : "+f"(c[0]), "+f"(c[1]), "+f"(c[2]), "+f"(c[3])
    : "r"(a[0]), "r"(a[1]), "r"(a[2]), "r"(a[3]), "r"(b[0]), "r"(b[1]));
}

// ============================================================================
// GEMM1: h[g,b,:] = z[b,:] @ W1[g] + b1[g]   (M=4096, N=2048, K=1024 per g)
// BM=128 BN=128 BK=32, 8 warps (4m x 2n), warp tile 32x64
// ============================================================================
__global__ void __launch_bounds__(256,1) k_gemm1(
    const float* __restrict__ z, const float* __restrict__ W1, const float* __restrict__ b1)
{
  const int g  = blockIdx.z;
  const int m0 = blockIdx.y * 128;
  const int n0 = blockIdx.x * 128;
  const float* Ag = z  + (size_t)m0 * NIN;
  const float* Bg = W1 + (size_t)g * NIN * NHID + n0;

  __shared__ unsigned As[128*36];   // [m][k], stride 36 (pad) — tf32 bits
  __shared__ unsigned Bs[32*132];   // [k][n], stride 132 (pad)

  const int tid  = threadIdx.x;
  const int lane = tid & 31, wid = tid >> 5;
  const int gid  = lane >> 2, tig = lane & 3;
  const int wm   = (wid & 3) * 32;
  const int wn   = (wid >> 2) * 64;

  float c[2][8][4];
  #pragma unroll
  for (int i=0;i<2;i++)
    #pragma unroll
    for (int j=0;j<8;j++)
      #pragma unroll
      for (int k=0;k<4;k++) c[i][j][k]=0.f;

  const int am = tid >> 3, akc = (tid & 7) << 2;   // A: 4 float4/thr, rows am+32i
  const int bk = tid >> 5, bnc = (tid & 31) << 2;  // B: 4 float4/thr, rows bk+8i

  float4 ra[4], rb[4];
  #pragma unroll
  for (int i=0;i<4;i++) ra[i] = *(const float4*)(Ag + (size_t)(am + 32*i)*NIN  + akc);
  #pragma unroll
  for (int i=0;i<4;i++) rb[i] = *(const float4*)(Bg + (size_t)(bk +  8*i)*NHID + bnc);

  const int KT = NIN / 32;
  for (int kt = 0; kt < KT; kt++) {
    #pragma unroll
    for (int i=0;i<4;i++){
      unsigned* p = &As[(am + 32*i)*36 + akc];
      p[0]=f2tf(ra[i].x); p[1]=f2tf(ra[i].y); p[2]=f2tf(ra[i].z); p[3]=f2tf(ra[i].w);
    }
    #pragma unroll
    for (int i=0;i<4;i++){
      unsigned* p = &Bs[(bk + 8*i)*132 + bnc];
      p[0]=f2tf(rb[i].x); p[1]=f2tf(rb[i].y); p[2]=f2tf(rb[i].z); p[3]=f2tf(rb[i].w);
    }
    __syncthreads();
    if (kt+1 < KT) {
      const float* An = Ag + (kt+1)*32;
      const float* Bn = Bg + (size_t)(kt+1)*32*NHID;
      #pragma unroll
      for (int i=0;i<4;i++) ra[i] = *(const float4*)(An + (size_t)(am+32*i)*NIN  + akc);
      #pragma unroll
      for (int i=0;i<4;i++) rb[i] = *(const float4*)(Bn + (size_t)(bk+ 8*i)*NHID + bnc);
    }
    #pragma unroll
    for (int ks=0;ks<4;ks++){
      const int kb = ks*8;
      unsigned a[2][4], b[8][2];
      #pragma unroll
      for (int mt=0;mt<2;mt++){
        const int r = wm + mt*16 + gid;
        a[mt][0] = As[(r  )*36 + kb + tig];
        a[mt][1] = As[(r+8)*36 + kb + tig];
        a[mt][2] = As[(r  )*36 + kb + tig + 4];
        a[mt][3] = As[(r+8)*36 + kb + tig + 4];
      }
      #pragma unroll
      for (int nt=0;nt<8;nt++){
        const int n = wn + nt*8 + gid;
        b[nt][0] = Bs[(kb+tig  )*132 + n];
        b[nt][1] = Bs[(kb+tig+4)*132 + n];
      }
      #pragma unroll
      for (int mt=0;mt<2;mt++)
        #pragma unroll
        for (int nt=0;nt<8;nt++)
          mma8(c[mt][nt], a[mt], b[nt]);
    }
    __syncthreads();
  }

  const float* b1g = b1 + g*NHID + n0;
  float* H = g_h + ((size_t)g*NB + m0) * NHID + n0;
  #pragma unroll
  for (int mt=0;mt<2;mt++){
    #pragma unroll
    for (int half=0; half<2; half++){
      const int r = wm + mt*16 + half*8 + gid;
      #pragma unroll
      for (int nt=0;nt<8;nt++){
        const int n = wn + nt*8 + tig*2;
        float2 v;
        v.x = c[mt][nt][half*2+0] + b1g[n];
        v.y = c[mt][nt][half*2+1] + b1g[n+1];
        *(float2*)(H + (size_t)r*NHID + n) = v;
      }
    }
  }
}

// ============================================================================
// K2: per-row LayerNorm + exact-erf GELU, in place on g_h. 1 block / row.
// ============================================================================
__global__ void __launch_bounds__(256) k_lngelu(
    const float* __restrict__ ln_g, const float* __restrict__ ln_b)
{
  const int row = blockIdx.x;           // 0 .. G*B-1
  const int g   = row >> 12;            // B = 4096 rows per group
  float* base = g_h + (size_t)row * NHID;
  const int tid = threadIdx.x;
  const int lane = tid & 31, wid = tid >> 5;

  float4 v0 = ((const float4*)base)[tid];
  float4 v1 = ((const float4*)base)[tid + 256];
  float s = v0.x+v0.y+v0.z+v0.w + v1.x+v1.y+v1.z+v1.w;
  float q = v0.x*v0.x+v0.y*v0.y+v0.z*v0.z+v0.w*v0.w
          + v1.x*v1.x+v1.y*v1.y+v1.z*v1.z+v1.w*v1.w;
  #pragma unroll
  for (int o=16;o;o>>=1){
    s += __shfl_xor_sync(0xffffffffu, s, o);
    q += __shfl_xor_sync(0xffffffffu, q, o);
  }
  __shared__ float rs[8], rq[8];
  if (lane==0){ rs[wid]=s; rq[wid]=q; }
  __syncthreads();
  if (tid==0){
    float S=0.f, Q=0.f;
    #pragma unroll
    for (int i=0;i<8;i++){ S+=rs[i]; Q+=rq[i]; }
    rs[0]=S; rq[0]=Q;
  }
  __syncthreads();
  const float S = rs[0], Q = rq[0];
  const float mu   = S * (1.f/NHID);
  const float var  = Q * (1.f/NHID) - mu*mu;
  const float rsig = rsqrtf(var + 1e-5f);

  const float* lg = ln_g + g*NHID;
  const float* lb = ln_b + g*NHID;
  const float isq2 = 0.70710678118654752440f;

  const int c0 = tid*4, c1 = (tid+256)*4;
  float xs[8] = {v0.x,v0.y,v0.z,v0.w, v1.x,v1.y,v1.z,v1.w};
  int   cs[8] = {c0,c0+1,c0+2,c0+3, c1,c1+1,c1+2,c1+3};
  float ys[8];
  #pragma unroll
  for (int i=0;i<8;i++){
    float y = (xs[i]-mu)*rsig*lg[cs[i]] + lb[cs[i]];
    ys[i] = 0.5f*y*(1.f + erff(y*isq2));
  }
  ((float4*)base)[tid]       = make_float4(ys[0],ys[1],ys[2],ys[3]);
  ((float4*)base)[tid + 256] = make_float4(ys[4],ys[5],ys[6],ys[7]);
}

// ============================================================================
// K3: coef[g,v] = min(exp(logit_scale[g]),100) / max(||Wv[g,v,:]||, 1e-12)
// ============================================================================
__global__ void __launch_bounds__(256) k_coef(
    const float* __restrict__ Wv, const float* __restrict__ logit_scale)
{
  const int tid = threadIdx.x;
  const int wid = tid >> 5, lane = tid & 31;
  const int row = blockIdx.x * 8 + wid;     // 0 .. G*CHUNK-1
  const float* p = Wv + (size_t)row * NPROJ;
  float4 a = ((const float4*)p)[lane];
  float4 b = ((const float4*)p)[lane + 32];
  float s = a.x*a.x+a.y*a.y+a.z*a.z+a.w*a.w
          + b.x*b.x+b.y*b.y+b.z*b.z+b.w*b.w;
  #pragma unroll
  for (int o=16;o;o>>=1) s += __shfl_xor_sync(0xffffffffu, s, o);
  if (lane==0){
    const int g = row >> 12;                // CHUNK = 4096 rows per group
    const float sc = fminf(expf(logit_scale[g]), 100.f);
    g_coef[row] = sc / fmaxf(sqrtf(s), 1e-12f);
  }
}

// ============================================================================
// GEMM2: q = gelu_h @ W2 + b2, then row l2-normalize -> g_qn
// M=4096, N=256(full in block), K=2048 per g. BM=64 BN=256 BK=32,
// 8 warps (2m x 4n), warp tile 32x64. Deterministic smem row reduction.
// ============================================================================
__global__ void __launch_bounds__(256,1) k_gemm2(
    const float* __restrict__ W2, const float* __restrict__ b2)
{
  const int g  = blockIdx.z;
  const int m0 = blockIdx.y * 64;
  const float* Ag = g_h + ((size_t)g*NB + m0) * NHID;
  const float* Bg = W2  + (size_t)g * NHID * NPROJ;

  __shared__ unsigned As[64*36];
  __shared__ unsigned Bs[32*260];
  __shared__ float rp[64][4];
  __shared__ float sinv[64];

  const int tid  = threadIdx.x;
  const int lane = tid & 31, wid = tid >> 5;
  const int gid  = lane >> 2, tig = lane & 3;
  const int wm   = (wid & 1) * 32;
  const int wn   = (wid >> 1) * 64;

  float c[2][8][4];
  #pragma unroll
  for (int i=0;i<2;i++)
    #pragma unroll
    for (int j=0;j<8;j++)
      #pragma unroll
      for (int k=0;k<4;k++) c[i][j][k]=0.f;

  const int am = tid >> 3, akc = (tid & 7) << 2;   // A: 2 float4/thr, rows am+32i
  const int bk = tid >> 6, bnc = (tid & 63) << 2;  // B: 8 float4/thr, rows bk+4i

  float4 ra[2], rb[8];
  #pragma unroll
  for (int i=0;i<2;i++) ra[i] = *(const float4*)(Ag + (size_t)(am + 32*i)*NHID  + akc);
  #pragma unroll
  for (int i=0;i<8;i++) rb[i] = *(const float4*)(Bg + (size_t)(bk +  4*i)*NPROJ + bnc);

  const int KT = NHID / 32;
  for (int kt = 0; kt < KT; kt++) {
    #pragma unroll
    for (int i=0;i<2;i++){
      unsigned* p = &As[(am + 32*i)*36 + akc];
      p[0]=f2tf(ra[i].x); p[1]=f2tf(ra[i].y); p[2]=f2tf(ra[i].z); p[3]=f2tf(ra[i].w);
    }
    #pragma unroll
    for (int i=0;i<8;i++){
      unsigned* p = &Bs[(bk + 4*i)*260 + bnc];
      p[0]=f2tf(rb[i].x); p[1]=f2tf(rb[i].y); p[2]=f2tf(rb[i].z); p[3]=f2tf(rb[i].w);
    }
    __syncthreads();
    if (kt+1 < KT) {
      const float* An = Ag + (kt+1)*32;
      const float* Bn = Bg + (size_t)(kt+1)*32*NPROJ;
      #pragma unroll
      for (int i=0;i<2;i++) ra[i] = *(const float4*)(An + (size_t)(am+32*i)*NHID  + akc);
      #pragma unroll
      for (int i=0;i<8;i++) rb[i] = *(const float4*)(Bn + (size_t)(bk+ 4*i)*NPROJ + bnc);
    }
    #pragma unroll
    for (int ks=0;ks<4;ks++){
      const int kb = ks*8;
      unsigned a[2][4], b[8][2];
      #pragma unroll
      for (int mt=0;mt<2;mt++){
        const int r = wm + mt*16 + gid;
        a[mt][0] = As[(r  )*36 + kb + tig];
        a[mt][1] = As[(r+8)*36 + kb + tig];
        a[mt][2] = As[(r  )*36 + kb + tig + 4];
        a[mt][3] = As[(r+8)*36 + kb + tig + 4];
      }
      #pragma unroll
      for (int nt=0;nt<8;nt++){
        const int n = wn + nt*8 + gid;
        b[nt][0] = Bs[(kb+tig  )*260 + n];
        b[nt][1] = Bs[(kb+tig+4)*260 + n];
      }
      #pragma unroll
      for (int mt=0;mt<2;mt++)
        #pragma unroll
        for (int nt=0;nt<8;nt++)
          mma8(c[mt][nt], a[mt], b[nt]);
    }
    __syncthreads();
  }

  // + b2, then per-row sum of squares (deterministic: shfl within 4-lane group,
  // then fixed smem slots), then normalize and store.
  const float* b2g = b2 + g*NPROJ;
  #pragma unroll
  for (int mt=0;mt<2;mt++)
    #pragma unroll
    for (int nt=0;nt<8;nt++){
      const int n = wn + nt*8 + tig*2;
      c[mt][nt][0] += b2g[n];
      c[mt][nt][1] += b2g[n+1];
      c[mt][nt][2] += b2g[n];
      c[mt][nt][3] += b2g[n+1];
    }
  #pragma unroll
  for (int mt=0;mt<2;mt++)
    #pragma unroll
    for (int half=0;half<2;half++){
      float ps = 0.f;
      #pragma unroll
      for (int nt=0;nt<8;nt++){
        float x = c[mt][nt][half*2+0], y = c[mt][nt][half*2+1];
        ps += x*x + y*y;
      }
      ps += __shfl_xor_sync(0xffffffffu, ps, 1);
      ps += __shfl_xor_sync(0xffffffffu, ps, 2);
      if (tig==0) rp[wm + mt*16 + half*8 + gid][wid>>1] = ps;
    }
  __syncthreads();
  if (tid < 64){
    const float ss = rp[tid][0]+rp[tid][1]+rp[tid][2]+rp[tid][3];
    sinv[tid] = 1.f / fmaxf(sqrtf(ss), 1e-12f);
  }
  __syncthreads();
  float* Qp = g_qn + ((size_t)g*NB + m0) * NPROJ;
  #pragma unroll
  for (int mt=0;mt<2;mt++)
    #pragma unroll
    for (int half=0;half<2;half++){
      const int r = wm + mt*16 + half*8 + gid;
      const float inv = sinv[r];
      #pragma unroll
      for (int nt=0;nt<8;nt++){
        const int n = wn + nt*8 + tig*2;
        float2 v;
        v.x = c[mt][nt][half*2+0]*inv;
        v.y = c[mt][nt][half*2+1]*inv;
        *(float2*)(Qp + (size_t)r*NPROJ + n) = v;
      }
    }
}

// ============================================================================
// GEMM3: out[b, g*CHUNK+v] = (qn . Wv[g,v]) * coef[g,v] + bv[g,v]
// M=4096, N=4096, K=256 per g. BM=128 BN=128 BK=32. B transposed on smem store.
// ============================================================================
__global__ void __launch_bounds__(256,1) k_gemm3(
    const float* __restrict__ Wv, const float* __restrict__ bv, float* __restrict__ out)
{
  const int g  = blockIdx.z;
  const int m0 = blockIdx.y * 128;
  const int n0 = blockIdx.x * 128;
  const float* Ag = g_qn + ((size_t)g*NB + m0) * NPROJ;
  const float* Bg = Wv   + ((size_t)g*NCHUNK + n0) * NPROJ;

  __shared__ unsigned As[128*36];
  __shared__ unsigned Bs[32*132];

  const int tid  = threadIdx.x;
  const int lane = tid & 31, wid = tid >> 5;
  const int gid  = lane >> 2, tig = lane & 3;
  const int wm   = (wid & 3) * 32;
  const int wn   = (wid >> 2) * 64;

  float c[2][8][4];
  #pragma unroll
  for (int i=0;i<2;i++)
    #pragma unroll
    for (int j=0;j<8;j++)
      #pragma unroll
      for (int k=0;k<4;k++) c[i][j][k]=0.f;

  const int am = tid >> 3, akc = (tid & 7) << 2;   // A rows am+32i, k cols akc..+3
  const int bn = tid >> 3, bkc = (tid & 7) << 2;   // B rows(n) bn+32i, k cols bkc..+3

  float4 ra[4], rb[4];
  #pragma unroll
  for (int i=0;i<4;i++) ra[i] = *(const float4*)(Ag + (size_t)(am + 32*i)*NPROJ + akc);
  #pragma unroll
  for (int i=0;i<4;i++) rb[i] = *(const float4*)(Bg + (size_t)(bn + 32*i)*NPROJ + bkc);

  const int KT = NPROJ / 32;     // 8
  for (int kt = 0; kt < KT; kt++) {
    #pragma unroll
    for (int i=0;i<4;i++){
      unsigned* p = &As[(am + 32*i)*36 + akc];
      p[0]=f2tf(ra[i].x); p[1]=f2tf(ra[i].y); p[2]=f2tf(ra[i].z); p[3]=f2tf(ra[i].w);
    }
    #pragma unroll
    for (int i=0;i<4;i++){     // transpose Wv tile into [k][n]
      const int n = bn + 32*i;
      Bs[(bkc+0)*132 + n] = f2tf(rb[i].x);
      Bs[(bkc+1)*132 + n] = f2tf(rb[i].y);
      Bs[(bkc+2)*132 + n] = f2tf(rb[i].z);
      Bs[(bkc+3)*132 + n] = f2tf(rb[i].w);
    }
    __syncthreads();
    if (kt+1 < KT) {
      const float* An = Ag + (kt+1)*32;
      const float* Bn = Bg + (kt+1)*32;
      #pragma unroll
      for (int i=0;i<4;i++) ra[i] = *(const float4*)(An + (size_t)(am+32*i)*NPROJ + akc);
      #pragma unroll
      for (int i=0;i<4;i++) rb[i] = *(const float4*)(Bn + (size_t)(bn+32*i)*NPROJ + bkc);
    }
    #pragma unroll
    for (int ks=0;ks<4;ks++){
      const int kb = ks*8;
      unsigned a[2][4], b[8][2];
      #pragma unroll
      for (int mt=0;mt<2;mt++){
        const int r = wm + mt*16 + gid;
        a[mt][0] = As[(r  )*36 + kb + tig];
        a[mt][1] = As[(r+8)*36 + kb + tig];
        a[mt][2] = As[(r  )*36 + kb + tig + 4];
        a[mt][3] = As[(r+8)*36 + kb + tig + 4];
      }
      #pragma unroll
      for (int nt=0;nt<8;nt++){
        const int n = wn + nt*8 + gid;
        b[nt][0] = Bs[(kb+tig  )*132 + n];
        b[nt][1] = Bs[(kb+tig+4)*132 + n];
      }
      #pragma unroll
      for (int mt=0;mt<2;mt++)
        #pragma unroll
        for (int nt=0;nt<8;nt++)
          mma8(c[mt][nt], a[mt], b[nt]);
    }
    __syncthreads();
  }

  const float* cf  = g_coef + g*NCHUNK + n0;
  const float* bvg = bv     + g*NCHUNK + n0;
  float* O = out + (size_t)m0 * OUTLD + (size_t)g*NCHUNK + n0;
  #pragma unroll
  for (int mt=0;mt<2;mt++){
    #pragma unroll
    for (int half=0; half<2; half++){
      const int r = wm + mt*16 + half*8 + gid;
      #pragma unroll
      for (int nt=0;nt<8;nt++){
        const int n = wn + nt*8 + tig*2;
        float2 v;
        v.x = c[mt][nt][half*2+0]*cf[n]   + bvg[n];
        v.y = c[mt][nt][half*2+1]*cf[n+1] + bvg[n+1];
        *(float2*)(O + (size_t)r*OUTLD + n) = v;
      }
    }
  }
}

// ============================================================================
extern "C" void kernel_launch(void* const* d_in, const int* in_sizes, int n_in,
                              void* d_out, int out_size)
{
  (void)in_sizes; (void)n_in; (void)out_size;
  const float* z   = (const float*)d_in[0];
  const float* W1  = (const float*)d_in[1];
  const float* b1  = (const float*)d_in[2];
  const float* lng = (const float*)d_in[3];
  const float* lnb = (const float*)d_in[4];
  const float* W2  = (const float*)d_in[5];
  const float* b2  = (const float*)d_in[6];
  const float* Wv  = (const float*)d_in[7];
  const float* bv  = (const float*)d_in[8];
  const float* ls  = (const float*)d_in[9];
  float* out = (float*)d_out;

  k_gemm1 <<<dim3(NHID/128, NB/128, NG), 256>>>(z, W1, b1);
  k_lngelu<<<NG*NB, 256>>>(lng, lnb);
  k_coef  <<<NG*NCHUNK/8, 256>>>(Wv, ls);
  k_gemm2 <<<dim3(1, NB/64, NG), 256>>>(W2, b2);
  k_gemm3 <<<dim3(NCHUNK/128, NB/128, NG), 256>>>(Wv, bv, out);
}

// round 4
// speedup vs baseline: 1.5098x; 1.5098x over previous
#include <cuda_runtime.h>
#include <cuda_bf16.h>
#include <math.h>

#define NB     4096
#define NG     16
#define NIN    1024
#define NHID   2048
#define NPROJ  256
#define NCHUNK 4096
#define OUTLD  (NG*NCHUNK)   /* 65536 */

// Scratch (device globals — no allocation allowed)
__device__ float g_h[(size_t)NG*NB*NHID];        // 512 MB
__device__ float g_qn[(size_t)NG*NB*NPROJ];      // 16 MB
__device__ float g_coef[NG*NCHUNK];              // 256 KB
__device__ float g_w1t[(size_t)NG*NHID*NIN];     // 128 MB  W1 transposed: [g][n][k]
__device__ float g_w2t[(size_t)NG*NPROJ*NHID];   // 8 MB    W2 transposed: [g][p][h]

// ---------------------------------------------------------------------------
#define ASTRIDE 36                 /* 32 + 4 pad; 36*4 = 144 ≡ 16 (mod 128) */
#define ASZ (128*ASTRIDE)
#define BSZ (256*ASTRIDE)
#define SMEM_BYTES ((3*ASZ + 3*BSZ)*4)   /* 165,888 B */

__device__ __forceinline__ unsigned s2u(const void* p){
  return (unsigned)__cvta_generic_to_shared(p);
}
__device__ __forceinline__ void cpa16(void* s, const void* g){
  asm volatile("cp.async.cg.shared.global [%0], [%1], 16;\n"
    :: "r"(s2u(s)), "l"(g));
}
__device__ __forceinline__ void ldsm4(unsigned &r0, unsigned &r1, unsigned &r2, unsigned &r3, unsigned addr){
  asm volatile("ldmatrix.sync.aligned.m8n8.x4.shared.b16 {%0,%1,%2,%3}, [%4];\n"
    : "=r"(r0), "=r"(r1), "=r"(r2), "=r"(r3) : "r"(addr) : "memory");
}
__device__ __forceinline__ void mma8(float* c, const unsigned* a, const unsigned* b){
  asm volatile(
    "mma.sync.aligned.m16n8k8.row.col.f32.tf32.tf32.f32 "
    "{%0,%1,%2,%3}, {%4,%5,%6,%7}, {%8,%9}, {%0,%1,%2,%3};\n"
    : "+f"(c[0]), "+f"(c[1]), "+f"(c[2]), "+f"(c[3])
    : "r"(a[0]), "r"(a[1]), "r"(a[2]), "r"(a[3]), "r"(b[0]), "r"(b[1]));
}

// ---------------------------------------------------------------------------
// Shared mainloop. Block tile 128(M) x 256(N), BK=32, 256 threads.
// Warp grid 2(m) x 4(n); warp tile 64x64 (mt=4 x nt=8 of m16n8).
// A in smem [m][k] (k-contig), B in smem [n][k] (k-contig), both cp.async'd.
// Fragments via ldmatrix.x4 (tf32 bits reinterpreted as b16 pairs).
// ---------------------------------------------------------------------------
__device__ __forceinline__ void mma_tile_loop(
  const float* __restrict__ Ap, const float* __restrict__ Bp,
  int lda, int ldb, int KT, float* sm, float (&c)[4][8][4])
{
  const int tid  = threadIdx.x;
  const int lane = tid & 31, wid = tid >> 5;
  const int wm   = (wid & 1) * 64;
  const int wn   = (wid >> 1) * 64;
  const int srow = tid >> 3, scol = (tid & 7) << 2;

  #pragma unroll
  for (int i=0;i<4;i++)
    #pragma unroll
    for (int j=0;j<8;j++)
      #pragma unroll
      for (int k=0;k<4;k++) c[i][j][k]=0.f;

  auto issue = [&](int s, int k0){
    float* as = sm + s*ASZ;
    float* bs = sm + 3*ASZ + s*BSZ;
    #pragma unroll
    for (int i=0;i<4;i++)
      cpa16(&as[(srow+32*i)*ASTRIDE + scol], Ap + (size_t)(srow+32*i)*lda + k0 + scol);
    #pragma unroll
    for (int i=0;i<8;i++)
      cpa16(&bs[(srow+32*i)*ASTRIDE + scol], Bp + (size_t)(srow+32*i)*ldb + k0 + scol);
    asm volatile("cp.async.commit_group;\n" ::: "memory");
  };
  issue(0, 0);
  issue(1, 32);

  // per-lane fragment address components
  const int a_r  = lane & 15;            // row within 16-row m-tile
  const int a_c4 = (lane >> 4) * 4;      // k sub-block 0 / 4
  const int b_r  = (lane & 7) + ((lane >> 4) & 1) * 8;  // n row within 16-n pair
  const int b_c4 = ((lane >> 3) & 1) * 4;               // k sub-block 0 / 4

  for (int kt = 0; kt < KT; kt++){
    asm volatile("cp.async.wait_group 1;\n" ::: "memory");
    __syncthreads();
    if (kt+2 < KT) issue((kt+2)%3, (kt+2)*32);
    else asm volatile("cp.async.commit_group;\n" ::: "memory");

    const unsigned as0 = s2u(sm + (kt%3)*ASZ);
    const unsigned bs0 = s2u(sm + 3*ASZ + (kt%3)*BSZ);
    #pragma unroll
    for (int ks=0; ks<4; ks++){
      const int kb = ks*8;
      unsigned a[4][4], b[4][4];
      #pragma unroll
      for (int mt=0;mt<4;mt++){
        unsigned ad = as0 + (unsigned)(((wm + mt*16 + a_r)*ASTRIDE + kb + a_c4)*4);
        ldsm4(a[mt][0],a[mt][1],a[mt][2],a[mt][3], ad);
      }
      #pragma unroll
      for (int np=0;np<4;np++){
        unsigned bd = bs0 + (unsigned)(((wn + np*16 + b_r)*ASTRIDE + kb + b_c4)*4);
        ldsm4(b[np][0],b[np][1],b[np][2],b[np][3], bd);
      }
      #pragma unroll
      for (int mt=0;mt<4;mt++)
        #pragma unroll
        for (int np=0;np<4;np++){
          mma8(c[mt][np*2+0], a[mt], &b[np][0]);
          mma8(c[mt][np*2+1], a[mt], &b[np][2]);
        }
    }
  }
  __syncthreads();
}

// ---------------------------------------------------------------------------
// Transpose: src [g][R][C] -> dst [g][C][R]
// ---------------------------------------------------------------------------
__global__ void k_tr(const float* __restrict__ src, float* __restrict__ dst, int R, int C)
{
  __shared__ float t[32][33];
  const int g = blockIdx.z;
  src += (size_t)g*R*C;
  dst += (size_t)g*R*C;
  const int c0 = blockIdx.x*32, r0 = blockIdx.y*32;
  const int x = threadIdx.x, y = threadIdx.y;
  #pragma unroll
  for (int j=0;j<32;j+=8)
    t[y+j][x] = src[(size_t)(r0+y+j)*C + c0+x];
  __syncthreads();
  #pragma unroll
  for (int j=0;j<32;j+=8)
    dst[(size_t)(c0+y+j)*R + r0+x] = t[x][y+j];
}

// ---------------------------------------------------------------------------
// GEMM1: h = z @ W1 + b1   (A=z [4096][1024], B=w1t [g][2048][1024])
// ---------------------------------------------------------------------------
__global__ void __launch_bounds__(256,1) k_gemm1(
    const float* __restrict__ z, const float* __restrict__ b1)
{
  extern __shared__ float sm[];
  const int g  = blockIdx.z;
  const int m0 = blockIdx.y * 128;
  const int n0 = blockIdx.x * 256;
  const float* Ap = z + (size_t)m0 * NIN;
  const float* Bp = g_w1t + (size_t)g*NHID*NIN + (size_t)n0*NIN;

  float c[4][8][4];
  mma_tile_loop(Ap, Bp, NIN, NIN, NIN/32, sm, c);

  const int lane = threadIdx.x & 31, wid = threadIdx.x >> 5;
  const int wm = (wid & 1)*64, wn = (wid >> 1)*64;
  const int gid = lane >> 2, tig = lane & 3;
  const float* b1g = b1 + g*NHID + n0;
  float* H = g_h + ((size_t)g*NB + m0) * NHID + n0;
  #pragma unroll
  for (int mt=0;mt<4;mt++)
    #pragma unroll
    for (int half=0; half<2; half++){
      const int r = wm + mt*16 + half*8 + gid;
      #pragma unroll
      for (int nt=0;nt<8;nt++){
        const int n = wn + nt*8 + tig*2;
        float2 v;
        v.x = c[mt][nt][half*2+0] + b1g[n];
        v.y = c[mt][nt][half*2+1] + b1g[n+1];
        *(float2*)(H + (size_t)r*NHID + n) = v;
      }
    }
}

// ---------------------------------------------------------------------------
// K2: per-row LayerNorm + exact-erf GELU, in place on g_h. 1 block / row.
// ---------------------------------------------------------------------------
__global__ void __launch_bounds__(256) k_lngelu(
    const float* __restrict__ ln_g, const float* __restrict__ ln_b)
{
  const int row = blockIdx.x;           // 0 .. G*B-1
  const int g   = row >> 12;
  float* base = g_h + (size_t)row * NHID;
  const int tid = threadIdx.x;
  const int lane = tid & 31, wid = tid >> 5;

  float4 v0 = ((const float4*)base)[tid];
  float4 v1 = ((const float4*)base)[tid + 256];
  float s = v0.x+v0.y+v0.z+v0.w + v1.x+v1.y+v1.z+v1.w;
  float q = v0.x*v0.x+v0.y*v0.y+v0.z*v0.z+v0.w*v0.w
          + v1.x*v1.x+v1.y*v1.y+v1.z*v1.z+v1.w*v1.w;
  #pragma unroll
  for (int o=16;o;o>>=1){
    s += __shfl_xor_sync(0xffffffffu, s, o);
    q += __shfl_xor_sync(0xffffffffu, q, o);
  }
  __shared__ float rs[8], rq[8];
  if (lane==0){ rs[wid]=s; rq[wid]=q; }
  __syncthreads();
  if (tid==0){
    float S=0.f, Q=0.f;
    #pragma unroll
    for (int i=0;i<8;i++){ S+=rs[i]; Q+=rq[i]; }
    rs[0]=S; rq[0]=Q;
  }
  __syncthreads();
  const float S = rs[0], Q = rq[0];
  const float mu   = S * (1.f/NHID);
  const float var  = Q * (1.f/NHID) - mu*mu;
  const float rsig = rsqrtf(var + 1e-5f);

  const float* lg = ln_g + g*NHID;
  const float* lb = ln_b + g*NHID;
  const float isq2 = 0.70710678118654752440f;

  const int c0 = tid*4, c1 = (tid+256)*4;
  float xs[8] = {v0.x,v0.y,v0.z,v0.w, v1.x,v1.y,v1.z,v1.w};
  int   cs[8] = {c0,c0+1,c0+2,c0+3, c1,c1+1,c1+2,c1+3};
  float ys[8];
  #pragma unroll
  for (int i=0;i<8;i++){
    float y = (xs[i]-mu)*rsig*lg[cs[i]] + lb[cs[i]];
    ys[i] = 0.5f*y*(1.f + erff(y*isq2));
  }
  ((float4*)base)[tid]       = make_float4(ys[0],ys[1],ys[2],ys[3]);
  ((float4*)base)[tid + 256] = make_float4(ys[4],ys[5],ys[6],ys[7]);
}

// ---------------------------------------------------------------------------
// K3: coef[g,v] = min(exp(logit_scale[g]),100) / max(||Wv[g,v,:]||, 1e-12)
// ---------------------------------------------------------------------------
__global__ void __launch_bounds__(256) k_coef(
    const float* __restrict__ Wv, const float* __restrict__ logit_scale)
{
  const int tid = threadIdx.x;
  const int wid = tid >> 5, lane = tid & 31;
  const int row = blockIdx.x * 8 + wid;     // 0 .. G*CHUNK-1
  const float* p = Wv + (size_t)row * NPROJ;
  float4 a = ((const float4*)p)[lane];
  float4 b = ((const float4*)p)[lane + 32];
  float s = a.x*a.x+a.y*a.y+a.z*a.z+a.w*a.w
          + b.x*b.x+b.y*b.y+b.z*b.z+b.w*b.w;
  #pragma unroll
  for (int o=16;o;o>>=1) s += __shfl_xor_sync(0xffffffffu, s, o);
  if (lane==0){
    const int g = row >> 12;
    const float sc = fminf(expf(logit_scale[g]), 100.f);
    g_coef[row] = sc / fmaxf(sqrtf(s), 1e-12f);
  }
}

// ---------------------------------------------------------------------------
// GEMM2: q = gelu_h @ W2 + b2, row l2-normalize -> g_qn
// (A=g_h [g][4096][2048], B=w2t [g][256][2048], full N=256 in block)
// ---------------------------------------------------------------------------
__global__ void __launch_bounds__(256,1) k_gemm2(const float* __restrict__ b2)
{
  extern __shared__ float sm[];
  const int g  = blockIdx.z;
  const int m0 = blockIdx.y * 128;
  const float* Ap = g_h + ((size_t)g*NB + m0) * NHID;
  const float* Bp = g_w2t + (size_t)g*NPROJ*NHID;

  float c[4][8][4];
  mma_tile_loop(Ap, Bp, NHID, NHID, NHID/32, sm, c);

  const int tid = threadIdx.x;
  const int lane = tid & 31, wid = tid >> 5;
  const int wm = (wid & 1)*64, wn = (wid >> 1)*64;
  const int gid = lane >> 2, tig = lane & 3;

  float* rp   = sm;          // [128][4]
  float* sinv = sm + 512;    // [128]

  const float* b2g = b2 + g*NPROJ;
  #pragma unroll
  for (int mt=0;mt<4;mt++)
    #pragma unroll
    for (int half=0; half<2; half++){
      const int r = wm + mt*16 + half*8 + gid;
      float ps = 0.f;
      #pragma unroll
      for (int nt=0;nt<8;nt++){
        const int n = wn + nt*8 + tig*2;
        float x = c[mt][nt][half*2+0] + b2g[n];
        float y = c[mt][nt][half*2+1] + b2g[n+1];
        c[mt][nt][half*2+0] = x;
        c[mt][nt][half*2+1] = y;
        ps += x*x + y*y;
      }
      ps += __shfl_xor_sync(0xffffffffu, ps, 1);
      ps += __shfl_xor_sync(0xffffffffu, ps, 2);
      if (tig==0) rp[r*4 + (wid>>1)] = ps;
    }
  __syncthreads();
  if (tid < 128){
    const float ss = rp[tid*4+0]+rp[tid*4+1]+rp[tid*4+2]+rp[tid*4+3];
    sinv[tid] = 1.f / fmaxf(sqrtf(ss), 1e-12f);
  }
  __syncthreads();
  float* Qp = g_qn + ((size_t)g*NB + m0) * NPROJ;
  #pragma unroll
  for (int mt=0;mt<4;mt++)
    #pragma unroll
    for (int half=0; half<2; half++){
      const int r = wm + mt*16 + half*8 + gid;
      const float inv = sinv[r];
      #pragma unroll
      for (int nt=0;nt<8;nt++){
        const int n = wn + nt*8 + tig*2;
        float2 v;
        v.x = c[mt][nt][half*2+0]*inv;
        v.y = c[mt][nt][half*2+1]*inv;
        *(float2*)(Qp + (size_t)r*NPROJ + n) = v;
      }
    }
}

// ---------------------------------------------------------------------------
// GEMM3: out[b, g*CHUNK+v] = (qn . Wv[g,v]) * coef[g,v] + bv[g,v]
// (A=g_qn [g][4096][256], B=Wv [g][4096][256] already n-major)
// ---------------------------------------------------------------------------
__global__ void __launch_bounds__(256,1) k_gemm3(
    const float* __restrict__ Wv, const float* __restrict__ bv, float* __restrict__ out)
{
  extern __shared__ float sm[];
  const int g  = blockIdx.z;
  const int m0 = blockIdx.y * 128;
  const int n0 = blockIdx.x * 256;
  const float* Ap = g_qn + ((size_t)g*NB + m0) * NPROJ;
  const float* Bp = Wv + ((size_t)g*NCHUNK + n0) * NPROJ;

  float c[4][8][4];
  mma_tile_loop(Ap, Bp, NPROJ, NPROJ, NPROJ/32, sm, c);

  const int lane = threadIdx.x & 31, wid = threadIdx.x >> 5;
  const int wm = (wid & 1)*64, wn = (wid >> 1)*64;
  const int gid = lane >> 2, tig = lane & 3;

  const float* cf  = g_coef + g*NCHUNK + n0;
  const float* bvg = bv     + g*NCHUNK + n0;
  float* O = out + (size_t)m0 * OUTLD + (size_t)g*NCHUNK + n0;
  #pragma unroll
  for (int mt=0;mt<4;mt++)
    #pragma unroll
    for (int half=0; half<2; half++){
      const int r = wm + mt*16 + half*8 + gid;
      #pragma unroll
      for (int nt=0;nt<8;nt++){
        const int n = wn + nt*8 + tig*2;
        float2 v;
        v.x = c[mt][nt][half*2+0]*cf[n]   + bvg[n];
        v.y = c[mt][nt][half*2+1]*cf[n+1] + bvg[n+1];
        *(float2*)(O + (size_t)r*OUTLD + n) = v;
      }
    }
}

// ---------------------------------------------------------------------------
extern "C" void kernel_launch(void* const* d_in, const int* in_sizes, int n_in,
                              void* d_out, int out_size)
{
  (void)in_sizes; (void)n_in; (void)out_size;
  const float* z   = (const float*)d_in[0];
  const float* W1  = (const float*)d_in[1];
  const float* b1  = (const float*)d_in[2];
  const float* lng = (const float*)d_in[3];
  const float* lnb = (const float*)d_in[4];
  const float* W2  = (const float*)d_in[5];
  const float* b2  = (const float*)d_in[6];
  const float* Wv  = (const float*)d_in[7];
  const float* bv  = (const float*)d_in[8];
  const float* ls  = (const float*)d_in[9];
  float* out = (float*)d_out;

  cudaFuncSetAttribute(k_gemm1, cudaFuncAttributeMaxDynamicSharedMemorySize, SMEM_BYTES);
  cudaFuncSetAttribute(k_gemm2, cudaFuncAttributeMaxDynamicSharedMemorySize, SMEM_BYTES);
  cudaFuncSetAttribute(k_gemm3, cudaFuncAttributeMaxDynamicSharedMemorySize, SMEM_BYTES);

  float* w1t; cudaGetSymbolAddress((void**)&w1t, g_w1t);
  float* w2t; cudaGetSymbolAddress((void**)&w2t, g_w2t);

  // Pre-transpose weights to n-major (k-contiguous) layouts
  k_tr<<<dim3(NHID/32, NIN/32,  NG), dim3(32,8)>>>(W1, w1t, NIN,  NHID);
  k_tr<<<dim3(NPROJ/32, NHID/32, NG), dim3(32,8)>>>(W2, w2t, NHID, NPROJ);
  k_coef  <<<NG*NCHUNK/8, 256>>>(Wv, ls);

  k_gemm1 <<<dim3(NHID/256, NB/128, NG), 256, SMEM_BYTES>>>(z, b1);
  k_lngelu<<<NG*NB, 256>>>(lng, lnb);
  k_gemm2 <<<dim3(1, NB/128, NG), 256, SMEM_BYTES>>>(b2);
  k_gemm3 <<<dim3(NCHUNK/256, NB/128, NG), 256, SMEM_BYTES>>>(Wv, bv, out);
}